// round 3
// baseline (speedup 1.0000x reference)
#include <cuda_runtime.h>
#include <cuda_bf16.h>
#include <math_constants.h>

// ============================================================================
// Head: single-head causal attention. B=8, T=4096, C=768, D=64, fp32.
//   k = x@Wk; q = x@Wq; v = x@Wv
//   out = softmax(causal(q k^T / sqrt(64))) @ v
// Strategy (round 1): fp32 with packed fma.rn.f32x2 (Blackwell FFMA2, 2x fp32).
//   Kernel 1: fused-layout QKV projection GEMM -> __device__ scratch.
//   Kernel 2: flash attention, 64-row query tiles, 64-key kv tiles, online
//             base-2 softmax (scale*log2e folded into Q), O in registers.
// ============================================================================

#define B_   8
#define T_   4096
#define C_   768
#define D_   64
// (1/sqrt(64)) * log2(e): softmax computed in base 2 with one MUFU EX2 per p.
#define QSC  0.18033688011112042591f

typedef unsigned long long u64;

__device__ __forceinline__ u64 pk2(float lo, float hi) {
    u64 r; asm("mov.b64 %0, {%1, %2};" : "=l"(r) : "f"(lo), "f"(hi)); return r;
}
__device__ __forceinline__ void unpk2(u64 v, float& lo, float& hi) {
    asm("mov.b64 {%0, %1}, %2;" : "=f"(lo), "=f"(hi) : "l"(v));
}
__device__ __forceinline__ void fma2(u64& d, u64 a, u64 b) {
    asm("fma.rn.f32x2 %0, %1, %2, %0;" : "+l"(d) : "l"(a), "l"(b));
}
__device__ __forceinline__ u64 mul2(u64 a, u64 b) {
    u64 d; asm("mul.rn.f32x2 %0, %1, %2;" : "=l"(d) : "l"(a), "l"(b)); return d;
}
__device__ __forceinline__ float sum2(u64 v) {
    float lo, hi; unpk2(v, lo, hi); return lo + hi;
}
__device__ __forceinline__ float ex2(float x) {
    float r; asm("ex2.approx.f32 %0, %1;" : "=f"(r) : "f"(x)); return r;
}

// Scratch for projected q/k/v: 3 * 8*4096*64 fp32 = 24 MB (static, no allocs).
__device__ __align__(16) float g_q[B_ * T_ * D_];
__device__ __align__(16) float g_k[B_ * T_ * D_];
__device__ __align__(16) float g_v[B_ * T_ * D_];

// ============================================================================
// Kernel 1: projection GEMM. grid (512, 3): x=row-tile (64 rows), y=which W.
// Per block: C[64,64] = x_tile[64,768] @ W[768,64], k-chunked by 64.
// Thread (tr,tc) owns a 4x4 subtile; accumulators are f32x2 over k-parity.
// ============================================================================
__global__ void __launch_bounds__(256)
proj_kernel(const float* __restrict__ x,
            const float* __restrict__ Wk,
            const float* __restrict__ Wq,
            const float* __restrict__ Wv) {
    __shared__ __align__(16) float xs[64 * 68];  // [row][k], k contiguous
    __shared__ __align__(16) float ws[64 * 68];  // [k][col], col contiguous

    const int wy   = blockIdx.y;
    const float* W = (wy == 0) ? Wk : ((wy == 1) ? Wq : Wv);
    float* out     = (wy == 0) ? g_k : ((wy == 1) ? g_q : g_v);

    const int row0 = blockIdx.x * 64;
    const int tid  = threadIdx.x;
    const int tr   = tid >> 4;       // 0..15 -> rows tr*4..tr*4+3
    const int tc   = tid & 15;       // 0..15 -> cols tc*4..tc*4+3

    u64 acc[4][4];
#pragma unroll
    for (int i = 0; i < 4; i++)
#pragma unroll
        for (int j = 0; j < 4; j++) acc[i][j] = 0ull;

    for (int kc = 0; kc < C_; kc += 64) {
#pragma unroll
        for (int i = 0; i < 4; i++) {
            int e = i * 256 + tid;       // float4 slot 0..1023
            int r = e >> 4;              // 0..63
            int c = (e & 15) * 4;        // 0..60
            *(float4*)&xs[r * 68 + c] =
                *(const float4*)&x[(size_t)(row0 + r) * C_ + kc + c];
            *(float4*)&ws[r * 68 + c] =
                *(const float4*)&W[(size_t)(kc + r) * D_ + c];
        }
        __syncthreads();

#pragma unroll 4
        for (int k = 0; k < 64; k += 2) {
            u64 a2[4];
#pragma unroll
            for (int i = 0; i < 4; i++) {
                float2 av = *(float2*)&xs[(tr * 4 + i) * 68 + k];
                a2[i] = pk2(av.x, av.y);
            }
            float4 b0 = *(float4*)&ws[k * 68 + tc * 4];
            float4 b1 = *(float4*)&ws[(k + 1) * 68 + tc * 4];
            u64 b2[4] = { pk2(b0.x, b1.x), pk2(b0.y, b1.y),
                          pk2(b0.z, b1.z), pk2(b0.w, b1.w) };
#pragma unroll
            for (int i = 0; i < 4; i++)
#pragma unroll
                for (int j = 0; j < 4; j++) fma2(acc[i][j], a2[i], b2[j]);
        }
        __syncthreads();
    }

#pragma unroll
    for (int i = 0; i < 4; i++) {
        float4 r4;
        r4.x = sum2(acc[i][0]);
        r4.y = sum2(acc[i][1]);
        r4.z = sum2(acc[i][2]);
        r4.w = sum2(acc[i][3]);
        *(float4*)&out[(size_t)(row0 + tr * 4 + i) * D_ + tc * 4] = r4;
    }
}

// ============================================================================
// Kernel 2: flash attention. grid 512 = 8 batches x 64 query tiles (64 rows).
// Heaviest query tiles scheduled first (qt descending) for wave balance.
// Per kv tile (64 keys): S = Qs @ Kt (f32x2), base-2 online softmax, O update.
// ============================================================================

// Dynamic smem layout (floats):
//   Qs  [64][68]  @ 0       (row-major, k contiguous, pre-scaled by QSC)
//   Kt  [64][68]  @ 4352    (transposed: [k][col], col contiguous)
//   Vs  [64][64]  @ 8704    (natural: [key][d], d contiguous)
//   Ss  [64][68]  @ 12800   (scores / probabilities)
//   m_s [64]      @ 17152 ; l_s [64] @ 17216 ; a_s [64] @ 17280
#define ATTN_SMEM_FLOATS 17344
#define ATTN_SMEM_BYTES  (ATTN_SMEM_FLOATS * 4)

__global__ void __launch_bounds__(256, 2)
attn_kernel(float* __restrict__ out) {
    extern __shared__ __align__(16) float sm[];
    float* Qs  = sm;
    float* Kt  = sm + 4352;
    float* Vs  = sm + 8704;
    float* Ss  = sm + 12800;
    float* m_s = sm + 17152;
    float* l_s = sm + 17216;
    float* a_s = sm + 17280;

    const int bid = blockIdx.x;
    const int qt  = 63 - (bid >> 3);   // heavy tiles first
    const int b   = bid & 7;
    const int q0  = qt * 64;
    const int tid = threadIdx.x;
    const int tr  = tid >> 4;
    const int tc  = tid & 15;

    // Load Q tile with scale*log2e folded in.
#pragma unroll
    for (int i = 0; i < 4; i++) {
        int e = i * 256 + tid;
        int r = e >> 4;
        int c = (e & 15) * 4;
        float4 v = *(const float4*)&g_q[((size_t)b * T_ + q0 + r) * D_ + c];
        v.x *= QSC; v.y *= QSC; v.z *= QSC; v.w *= QSC;
        *(float4*)&Qs[r * 68 + c] = v;
    }
    if (tid < 64) { m_s[tid] = -CUDART_INF_F; l_s[tid] = 0.0f; }

    u64 o2[4][4];
#pragma unroll
    for (int i = 0; i < 4; i++)
#pragma unroll
        for (int j = 0; j < 4; j++) o2[i][j] = 0ull;

    for (int kt = 0; kt <= qt; kt++) {
        const int k0 = kt * 64;

        // Load K (transposed into Kt) and V (natural).
#pragma unroll
        for (int i = 0; i < 4; i++) {
            int e = i * 256 + tid;
            int r = e >> 4;
            int c = (e & 15) * 4;
            float4 kv = *(const float4*)&g_k[((size_t)b * T_ + k0 + r) * D_ + c];
            Kt[(c + 0) * 68 + r] = kv.x;
            Kt[(c + 1) * 68 + r] = kv.y;
            Kt[(c + 2) * 68 + r] = kv.z;
            Kt[(c + 3) * 68 + r] = kv.w;
            *(float4*)&Vs[r * 64 + c] =
                *(const float4*)&g_v[((size_t)b * T_ + k0 + r) * D_ + c];
        }
        __syncthreads();

        // S = Qs @ Kt  (thread owns 4x4; f32x2 accumulation over k-parity)
        u64 acc[4][4];
#pragma unroll
        for (int i = 0; i < 4; i++)
#pragma unroll
            for (int j = 0; j < 4; j++) acc[i][j] = 0ull;

#pragma unroll 4
        for (int k = 0; k < 64; k += 2) {
            u64 a2[4];
#pragma unroll
            for (int i = 0; i < 4; i++) {
                float2 av = *(float2*)&Qs[(tr * 4 + i) * 68 + k];
                a2[i] = pk2(av.x, av.y);
            }
            float4 b0 = *(float4*)&Kt[k * 68 + tc * 4];
            float4 b1 = *(float4*)&Kt[(k + 1) * 68 + tc * 4];
            u64 b2[4] = { pk2(b0.x, b1.x), pk2(b0.y, b1.y),
                          pk2(b0.z, b1.z), pk2(b0.w, b1.w) };
#pragma unroll
            for (int i = 0; i < 4; i++)
#pragma unroll
                for (int j = 0; j < 4; j++) fma2(acc[i][j], a2[i], b2[j]);
        }

#pragma unroll
        for (int i = 0; i < 4; i++) {
            float4 s4;
            s4.x = sum2(acc[i][0]);
            s4.y = sum2(acc[i][1]);
            s4.z = sum2(acc[i][2]);
            s4.w = sum2(acc[i][3]);
            *(float4*)&Ss[(tr * 4 + i) * 68 + tc * 4] = s4;
        }
        __syncthreads();

        // Online softmax: 4 threads per row, base-2.
        {
            const int row = tid >> 2;
            const int qq  = tid & 3;
            float* srow = &Ss[row * 68 + qq * 16];
            const bool diag = (kt == qt);

            float vb[16];
            float mx = -CUDART_INF_F;
#pragma unroll
            for (int u = 0; u < 16; u++) {
                float s = srow[u];
                if (diag && (qq * 16 + u) > row) s = -CUDART_INF_F;
                vb[u] = s;
                mx = fmaxf(mx, s);
            }
            mx = fmaxf(mx, __shfl_xor_sync(0xffffffffu, mx, 1));
            mx = fmaxf(mx, __shfl_xor_sync(0xffffffffu, mx, 2));

            float m_old = m_s[row];
            float m_new = fmaxf(m_old, mx);
            float alpha = ex2(m_old - m_new);   // exp2(-inf)=0 on first tile

            float ssum = 0.0f;
#pragma unroll
            for (int u = 0; u < 16; u++) {
                float p = ex2(vb[u] - m_new);
                srow[u] = p;
                ssum += p;
            }
            ssum += __shfl_xor_sync(0xffffffffu, ssum, 1);
            ssum += __shfl_xor_sync(0xffffffffu, ssum, 2);

            if (qq == 0) {
                m_s[row] = m_new;
                l_s[row] = l_s[row] * alpha + ssum;
                a_s[row] = alpha;
            }
        }
        __syncthreads();

        // O = O*alpha + P @ V
#pragma unroll
        for (int i = 0; i < 4; i++) {
            float al = a_s[tr * 4 + i];
            u64 al2 = pk2(al, al);
#pragma unroll
            for (int j = 0; j < 4; j++) o2[i][j] = mul2(o2[i][j], al2);
        }

#pragma unroll 4
        for (int jp = 0; jp < 64; jp += 2) {
            u64 a2[4];
#pragma unroll
            for (int i = 0; i < 4; i++) {
                float2 av = *(float2*)&Ss[(tr * 4 + i) * 68 + jp];
                a2[i] = pk2(av.x, av.y);
            }
            float4 b0 = *(float4*)&Vs[jp * 64 + tc * 4];
            float4 b1 = *(float4*)&Vs[(jp + 1) * 64 + tc * 4];
            u64 b2[4] = { pk2(b0.x, b1.x), pk2(b0.y, b1.y),
                          pk2(b0.z, b1.z), pk2(b0.w, b1.w) };
#pragma unroll
            for (int i = 0; i < 4; i++)
#pragma unroll
                for (int j = 0; j < 4; j++) fma2(o2[i][j], a2[i], b2[j]);
        }
        __syncthreads();
    }

    // Epilogue: normalize by l and store.
#pragma unroll
    for (int i = 0; i < 4; i++) {
        float linv = 1.0f / l_s[tr * 4 + i];
        float4 r4;
        r4.x = sum2(o2[i][0]) * linv;
        r4.y = sum2(o2[i][1]) * linv;
        r4.z = sum2(o2[i][2]) * linv;
        r4.w = sum2(o2[i][3]) * linv;
        *(float4*)&out[((size_t)b * T_ + q0 + tr * 4 + i) * D_ + tc * 4] = r4;
    }
}

// ============================================================================
extern "C" void kernel_launch(void* const* d_in, const int* in_sizes, int n_in,
                              void* d_out, int out_size) {
    const float* x  = (const float*)d_in[0];
    const float* Wk = (const float*)d_in[1];
    const float* Wq = (const float*)d_in[2];
    const float* Wv = (const float*)d_in[3];
    float* out = (float*)d_out;
    (void)in_sizes; (void)n_in; (void)out_size;

    // Opt in to >48KB dynamic smem (idempotent; set on every call).
    cudaFuncSetAttribute(attn_kernel,
                         cudaFuncAttributeMaxDynamicSharedMemorySize,
                         ATTN_SMEM_BYTES);

    proj_kernel<<<dim3((B_ * T_) / 64, 3), 256>>>(x, Wk, Wq, Wv);
    attn_kernel<<<B_ * (T_ / 64), 256, ATTN_SMEM_BYTES>>>(out);
}

// round 5
// speedup vs baseline: 1.2947x; 1.2947x over previous
#include <cuda_runtime.h>
#include <cuda_bf16.h>
#include <math_constants.h>

// ============================================================================
// Head: single-head causal attention. B=8, T=4096, C=768, D=64, fp32.
// Round 4 = Round 3 resubmit (infra failure, no measurement taken).
// Pure-f32x2 datapath: all GEMM operands live in smem in pair-interleaved
// layouts so every FFMA2 operand comes straight from an LDS.64/LDS.128 with
// zero mov.b64 packing. Softmax fully in registers via half-warp shuffles.
// ============================================================================

#define B_   8
#define T_   4096
#define C_   768
#define D_   64
// (1/sqrt(64)) * log2(e): softmax in base 2, one MUFU EX2 per probability.
#define QSC  0.18033688011112042591f

typedef unsigned long long u64;

__device__ __forceinline__ u64 pk2(float lo, float hi) {
    u64 r; asm("mov.b64 %0, {%1, %2};" : "=l"(r) : "f"(lo), "f"(hi)); return r;
}
__device__ __forceinline__ void fma2(u64& d, u64 a, u64 b) {
    asm("fma.rn.f32x2 %0, %1, %2, %0;" : "+l"(d) : "l"(a), "l"(b));
}
__device__ __forceinline__ u64 mul2(u64 a, u64 b) {
    u64 d; asm("mul.rn.f32x2 %0, %1, %2;" : "=l"(d) : "l"(a), "l"(b)); return d;
}
__device__ __forceinline__ float sum2(u64 v) {
    float lo, hi;
    asm("mov.b64 {%0, %1}, %2;" : "=f"(lo), "=f"(hi) : "l"(v));
    return lo + hi;
}
__device__ __forceinline__ float ex2(float x) {
    float r; asm("ex2.approx.f32 %0, %1;" : "=f"(r) : "f"(x)); return r;
}

// Scratch for projected q/k/v: 3 * 8*4096*64 fp32 = 24 MB (static, no allocs).
__device__ __align__(16) float g_q[B_ * T_ * D_];
__device__ __align__(16) float g_k[B_ * T_ * D_];
__device__ __align__(16) float g_v[B_ * T_ * D_];

// ============================================================================
// Kernel 1: projection GEMM. grid (512, 3). Per block: 64x64 out tile,
// k-chunks of 64. xs row-major (A, pair loads direct); ws2 = u64[32][66]
// pair-interleaved over k: ws2[kp][col] = (W[2kp][col], W[2kp+1][col]).
// Thread owns cols {2tc, 2tc+1, 32+2tc, 33+2tc} -> conflict-free LDS.128 B.
// ============================================================================
__global__ void __launch_bounds__(256)
proj_kernel(const float* __restrict__ x,
            const float* __restrict__ Wk,
            const float* __restrict__ Wq,
            const float* __restrict__ Wv) {
    __shared__ __align__(16) float xs[64 * 64];
    __shared__ __align__(16) u64   ws2[32 * 66];

    const int wy   = blockIdx.y;
    const float* W = (wy == 0) ? Wk : ((wy == 1) ? Wq : Wv);
    float* out     = (wy == 0) ? g_k : ((wy == 1) ? g_q : g_v);

    const int row0 = blockIdx.x * 64;
    const int tid  = threadIdx.x;
    const int tr4  = (tid >> 4) * 4;
    const int c0   = (tid & 15) * 2;       // owned cols: c0,c0+1,c0+32,c0+33

    u64 acc[4][4];
#pragma unroll
    for (int i = 0; i < 4; i++)
#pragma unroll
        for (int j = 0; j < 4; j++) acc[i][j] = 0ull;

    for (int kc = 0; kc < C_; kc += 64) {
        // x tile: straight float4 copy, row-major.
#pragma unroll
        for (int i = 0; i < 4; i++) {
            int slot = i * 256 + tid;
            int r = slot >> 4;
            int c = (slot & 15) * 4;
            *(float4*)&xs[r * 64 + c] =
                *(const float4*)&x[(size_t)(row0 + r) * C_ + kc + c];
        }
        // W tile: load two consecutive k-rows, pack pairs, store u64x2.
#pragma unroll
        for (int i = 0; i < 2; i++) {
            int sp = i * 256 + tid;
            int kp = sp >> 4;
            int c  = (sp & 15) * 4;
            const float* wr = &W[(size_t)(kc + 2 * kp) * D_ + c];
            float4 wA = *(const float4*)wr;
            float4 wB = *(const float4*)(wr + D_);
            ulonglong2 p0 = { pk2(wA.x, wB.x), pk2(wA.y, wB.y) };
            ulonglong2 p1 = { pk2(wA.z, wB.z), pk2(wA.w, wB.w) };
            *(ulonglong2*)&ws2[kp * 66 + c]     = p0;
            *(ulonglong2*)&ws2[kp * 66 + c + 2] = p1;
        }
        __syncthreads();

#pragma unroll 8
        for (int kp = 0; kp < 32; kp++) {
            u64 a0 = *(const u64*)&xs[(tr4 + 0) * 64 + 2 * kp];
            u64 a1 = *(const u64*)&xs[(tr4 + 1) * 64 + 2 * kp];
            u64 a2v = *(const u64*)&xs[(tr4 + 2) * 64 + 2 * kp];
            u64 a3 = *(const u64*)&xs[(tr4 + 3) * 64 + 2 * kp];
            ulonglong2 b01 = *(const ulonglong2*)&ws2[kp * 66 + c0];
            ulonglong2 b23 = *(const ulonglong2*)&ws2[kp * 66 + 32 + c0];
            fma2(acc[0][0], a0, b01.x); fma2(acc[0][1], a0, b01.y);
            fma2(acc[0][2], a0, b23.x); fma2(acc[0][3], a0, b23.y);
            fma2(acc[1][0], a1, b01.x); fma2(acc[1][1], a1, b01.y);
            fma2(acc[1][2], a1, b23.x); fma2(acc[1][3], a1, b23.y);
            fma2(acc[2][0], a2v, b01.x); fma2(acc[2][1], a2v, b01.y);
            fma2(acc[2][2], a2v, b23.x); fma2(acc[2][3], a2v, b23.y);
            fma2(acc[3][0], a3, b01.x); fma2(acc[3][1], a3, b01.y);
            fma2(acc[3][2], a3, b23.x); fma2(acc[3][3], a3, b23.y);
        }
        __syncthreads();
    }

#pragma unroll
    for (int i = 0; i < 4; i++) {
        float* orow = &out[(size_t)(row0 + tr4 + i) * D_];
        float2 r01 = { sum2(acc[i][0]), sum2(acc[i][1]) };
        float2 r23 = { sum2(acc[i][2]), sum2(acc[i][3]) };
        *(float2*)&orow[c0]      = r01;
        *(float2*)&orow[32 + c0] = r23;
    }
}

// ============================================================================
// Kernel 2: flash attention, all-register softmax.
// smem (floats): Qs[64*64] @0 | Ss[64*64] @4096 | Kt2 u64[32*66] @8192f |
//                Vs2 u64[32*66] @12416f.  Total 66560 bytes.
// ============================================================================
#define ATTN_SMEM_BYTES (16640 * 4)

__global__ void __launch_bounds__(256, 2)
attn_kernel(float* __restrict__ out) {
    extern __shared__ __align__(16) float sm[];
    float* Qs = sm;
    float* Ss = sm + 4096;
    u64*   Kt2 = (u64*)(sm + 8192);
    u64*   Vs2 = (u64*)(sm + 12416);

    const int bid = blockIdx.x;
    const int qt  = 63 - (bid >> 3);   // heaviest query tiles first
    const int b   = bid & 7;
    const int q0  = qt * 64;
    const int tid = threadIdx.x;
    const int tr4 = (tid >> 4) * 4;
    const int c0  = (tid & 15) * 2;

    // Q tile (scale*log2e folded in), row-major.
#pragma unroll
    for (int i = 0; i < 4; i++) {
        int slot = i * 256 + tid;
        int r = slot >> 4;
        int c = (slot & 15) * 4;
        float4 v = *(const float4*)&g_q[((size_t)b * T_ + q0 + r) * D_ + c];
        v.x *= QSC; v.y *= QSC; v.z *= QSC; v.w *= QSC;
        *(float4*)&Qs[r * 64 + c] = v;
    }

    float m[4], l[4];
#pragma unroll
    for (int i = 0; i < 4; i++) { m[i] = -CUDART_INF_F; l[i] = 0.0f; }

    u64 o2[4][4];
#pragma unroll
    for (int i = 0; i < 4; i++)
#pragma unroll
        for (int j = 0; j < 4; j++) o2[i][j] = 0ull;

    for (int kt = 0; kt <= qt; kt++) {
        const int k0 = kt * 64;

        // K tile -> Kt2[kp][key] = (K[key][2kp], K[key][2kp+1]).
#pragma unroll
        for (int i = 0; i < 4; i++) {
            int slot = i * 256 + tid;
            int r = slot >> 4;
            int c = (slot & 15) * 4;
            float4 kv = *(const float4*)&g_k[((size_t)b * T_ + k0 + r) * D_ + c];
            int kp0 = c >> 1;
            Kt2[kp0 * 66 + r]       = pk2(kv.x, kv.y);
            Kt2[(kp0 + 1) * 66 + r] = pk2(kv.z, kv.w);
        }
        // V tile -> Vs2[keyp][d] = (V[2keyp][d], V[2keyp+1][d]).
#pragma unroll
        for (int i = 0; i < 2; i++) {
            int sp = i * 256 + tid;
            int keyp = sp >> 4;
            int c = (sp & 15) * 4;
            const float* vr = &g_v[((size_t)b * T_ + k0 + 2 * keyp) * D_ + c];
            float4 vA = *(const float4*)vr;
            float4 vB = *(const float4*)(vr + D_);
            ulonglong2 p0 = { pk2(vA.x, vB.x), pk2(vA.y, vB.y) };
            ulonglong2 p1 = { pk2(vA.z, vB.z), pk2(vA.w, vB.w) };
            *(ulonglong2*)&Vs2[keyp * 66 + c]     = p0;
            *(ulonglong2*)&Vs2[keyp * 66 + c + 2] = p1;
        }
        __syncthreads();   // A: K/V (and Q on first iter) visible

        // ---- S = Q @ K^T, accumulate in f32x2 over d-pairs ----
        u64 acc[4][4];
#pragma unroll
        for (int i = 0; i < 4; i++)
#pragma unroll
            for (int j = 0; j < 4; j++) acc[i][j] = 0ull;

#pragma unroll 8
        for (int kp = 0; kp < 32; kp++) {
            u64 a0 = *(const u64*)&Qs[(tr4 + 0) * 64 + 2 * kp];
            u64 a1 = *(const u64*)&Qs[(tr4 + 1) * 64 + 2 * kp];
            u64 a2v = *(const u64*)&Qs[(tr4 + 2) * 64 + 2 * kp];
            u64 a3 = *(const u64*)&Qs[(tr4 + 3) * 64 + 2 * kp];
            ulonglong2 b01 = *(const ulonglong2*)&Kt2[kp * 66 + c0];
            ulonglong2 b23 = *(const ulonglong2*)&Kt2[kp * 66 + 32 + c0];
            fma2(acc[0][0], a0, b01.x); fma2(acc[0][1], a0, b01.y);
            fma2(acc[0][2], a0, b23.x); fma2(acc[0][3], a0, b23.y);
            fma2(acc[1][0], a1, b01.x); fma2(acc[1][1], a1, b01.y);
            fma2(acc[1][2], a1, b23.x); fma2(acc[1][3], a1, b23.y);
            fma2(acc[2][0], a2v, b01.x); fma2(acc[2][1], a2v, b01.y);
            fma2(acc[2][2], a2v, b23.x); fma2(acc[2][3], a2v, b23.y);
            fma2(acc[3][0], a3, b01.x); fma2(acc[3][1], a3, b01.y);
            fma2(acc[3][2], a3, b23.x); fma2(acc[3][3], a3, b23.y);
        }

        // ---- In-register online softmax (rows owned by 16-lane groups) ----
        float s[4][4];
#pragma unroll
        for (int i = 0; i < 4; i++) {
            s[i][0] = sum2(acc[i][0]);
            s[i][1] = sum2(acc[i][1]);
            s[i][2] = sum2(acc[i][2]);
            s[i][3] = sum2(acc[i][3]);
        }
        if (kt == qt) {
#pragma unroll
            for (int i = 0; i < 4; i++) {
                int row = tr4 + i;
                if (c0 + 0  > row) s[i][0] = -CUDART_INF_F;
                if (c0 + 1  > row) s[i][1] = -CUDART_INF_F;
                if (c0 + 32 > row) s[i][2] = -CUDART_INF_F;
                if (c0 + 33 > row) s[i][3] = -CUDART_INF_F;
            }
        }
#pragma unroll
        for (int i = 0; i < 4; i++) {
            float mx = fmaxf(fmaxf(s[i][0], s[i][1]), fmaxf(s[i][2], s[i][3]));
            mx = fmaxf(mx, __shfl_xor_sync(0xffffffffu, mx, 1));
            mx = fmaxf(mx, __shfl_xor_sync(0xffffffffu, mx, 2));
            mx = fmaxf(mx, __shfl_xor_sync(0xffffffffu, mx, 4));
            mx = fmaxf(mx, __shfl_xor_sync(0xffffffffu, mx, 8));

            float m_new = fmaxf(m[i], mx);
            float alpha = ex2(m[i] - m_new);   // exp2(-inf) = 0 on first tile
            m[i] = m_new;

            float p0 = ex2(s[i][0] - m_new);
            float p1 = ex2(s[i][1] - m_new);
            float p2 = ex2(s[i][2] - m_new);
            float p3 = ex2(s[i][3] - m_new);
            float ps = (p0 + p1) + (p2 + p3);
            ps += __shfl_xor_sync(0xffffffffu, ps, 1);
            ps += __shfl_xor_sync(0xffffffffu, ps, 2);
            ps += __shfl_xor_sync(0xffffffffu, ps, 4);
            ps += __shfl_xor_sync(0xffffffffu, ps, 8);
            l[i] = l[i] * alpha + ps;

            u64 al2 = pk2(alpha, alpha);
            o2[i][0] = mul2(o2[i][0], al2);
            o2[i][1] = mul2(o2[i][1], al2);
            o2[i][2] = mul2(o2[i][2], al2);
            o2[i][3] = mul2(o2[i][3], al2);

            int row = tr4 + i;
            float2 w01 = { p0, p1 };
            float2 w23 = { p2, p3 };
            *(float2*)&Ss[row * 64 + c0]      = w01;
            *(float2*)&Ss[row * 64 + 32 + c0] = w23;
        }
        __syncthreads();   // B: P visible

        // ---- O += P @ V (pairs over key dim) ----
#pragma unroll 8
        for (int kp = 0; kp < 32; kp++) {
            u64 a0 = *(const u64*)&Ss[(tr4 + 0) * 64 + 2 * kp];
            u64 a1 = *(const u64*)&Ss[(tr4 + 1) * 64 + 2 * kp];
            u64 a2v = *(const u64*)&Ss[(tr4 + 2) * 64 + 2 * kp];
            u64 a3 = *(const u64*)&Ss[(tr4 + 3) * 64 + 2 * kp];
            ulonglong2 b01 = *(const ulonglong2*)&Vs2[kp * 66 + c0];
            ulonglong2 b23 = *(const ulonglong2*)&Vs2[kp * 66 + 32 + c0];
            fma2(o2[0][0], a0, b01.x); fma2(o2[0][1], a0, b01.y);
            fma2(o2[0][2], a0, b23.x); fma2(o2[0][3], a0, b23.y);
            fma2(o2[1][0], a1, b01.x); fma2(o2[1][1], a1, b01.y);
            fma2(o2[1][2], a1, b23.x); fma2(o2[1][3], a1, b23.y);
            fma2(o2[2][0], a2v, b01.x); fma2(o2[2][1], a2v, b01.y);
            fma2(o2[2][2], a2v, b23.x); fma2(o2[2][3], a2v, b23.y);
            fma2(o2[3][0], a3, b01.x); fma2(o2[3][1], a3, b01.y);
            fma2(o2[3][2], a3, b23.x); fma2(o2[3][3], a3, b23.y);
        }
        __syncthreads();   // C: Ss/Vs2/Kt2 free for next tile
    }

    // Epilogue: normalize and store.
#pragma unroll
    for (int i = 0; i < 4; i++) {
        float linv = 1.0f / l[i];
        float* orow = &out[((size_t)b * T_ + q0 + tr4 + i) * D_];
        float2 r01 = { sum2(o2[i][0]) * linv, sum2(o2[i][1]) * linv };
        float2 r23 = { sum2(o2[i][2]) * linv, sum2(o2[i][3]) * linv };
        *(float2*)&orow[c0]      = r01;
        *(float2*)&orow[32 + c0] = r23;
    }
}

// ============================================================================
extern "C" void kernel_launch(void* const* d_in, const int* in_sizes, int n_in,
                              void* d_out, int out_size) {
    const float* x  = (const float*)d_in[0];
    const float* Wk = (const float*)d_in[1];
    const float* Wq = (const float*)d_in[2];
    const float* Wv = (const float*)d_in[3];
    float* out = (float*)d_out;
    (void)in_sizes; (void)n_in; (void)out_size;

    cudaFuncSetAttribute(attn_kernel,
                         cudaFuncAttributeMaxDynamicSharedMemorySize,
                         ATTN_SMEM_BYTES);

    proj_kernel<<<dim3((B_ * T_) / 64, 3), 256>>>(x, Wk, Wq, Wv);
    attn_kernel<<<B_ * (T_ / 64), 256, ATTN_SMEM_BYTES>>>(out);
}

// round 7
// speedup vs baseline: 1.3048x; 1.0078x over previous
#include <cuda_runtime.h>
#include <cuda_bf16.h>
#include <math_constants.h>

// ============================================================================
// Head: single-head causal attention. B=8, T=4096, C=768, D=64, fp32.
// Round 6 = Round 5 resubmit (infra failure, no measurement taken).
//  - A tiles (Qs/Ss/xs) padded to stride 68 floats -> conflict-free broadcast.
//  - A loaded as LDS.128 spanning 2 k-pairs (bitwise f32x2 pairs).
//  - K written TRANSPOSED by proj (g_kT[d][b*T+t]) so attn's K-fill is
//    coalesced loads + floor-rate ulonglong2 stores (no 4-phase transpose).
//  - QSC (scale*log2e) folded into proj's Q output.
// ============================================================================

#define B_   8
#define T_   4096
#define C_   768
#define D_   64
#define BT_  (B_ * T_)
#define QSC  0.18033688011112042591f

typedef unsigned long long u64;

__device__ __forceinline__ u64 pk2(float lo, float hi) {
    u64 r; asm("mov.b64 %0, {%1, %2};" : "=l"(r) : "f"(lo), "f"(hi)); return r;
}
__device__ __forceinline__ void fma2(u64& d, u64 a, u64 b) {
    asm("fma.rn.f32x2 %0, %1, %2, %0;" : "+l"(d) : "l"(a), "l"(b));
}
__device__ __forceinline__ u64 mul2(u64 a, u64 b) {
    u64 d; asm("mul.rn.f32x2 %0, %1, %2;" : "=l"(d) : "l"(a), "l"(b)); return d;
}
__device__ __forceinline__ float sum2(u64 v) {
    float lo, hi;
    asm("mov.b64 {%0, %1}, %2;" : "=f"(lo), "=f"(hi) : "l"(v));
    return lo + hi;
}
__device__ __forceinline__ float ex2(float x) {
    float r; asm("ex2.approx.f32 %0, %1;" : "=f"(r) : "f"(x)); return r;
}

// Scratch (static; no allocations). q: pre-scaled by QSC. kT: [d][b*T+t].
__device__ __align__(16) float g_q [BT_ * D_];
__device__ __align__(16) float g_kT[D_ * BT_];
__device__ __align__(16) float g_v [BT_ * D_];

// 16 FFMA2: one k-pair across the thread's 4x4 output subtile.
#define FMA_BLOCK(ACC, A0, A1, A2, A3, BA, BB)                                 \
    fma2(ACC[0][0], A0, BA.x); fma2(ACC[0][1], A0, BA.y);                      \
    fma2(ACC[0][2], A0, BB.x); fma2(ACC[0][3], A0, BB.y);                      \
    fma2(ACC[1][0], A1, BA.x); fma2(ACC[1][1], A1, BA.y);                      \
    fma2(ACC[1][2], A1, BB.x); fma2(ACC[1][3], A1, BB.y);                      \
    fma2(ACC[2][0], A2, BA.x); fma2(ACC[2][1], A2, BA.y);                      \
    fma2(ACC[2][2], A2, BB.x); fma2(ACC[2][3], A2, BB.y);                      \
    fma2(ACC[3][0], A3, BA.x); fma2(ACC[3][1], A3, BA.y);                      \
    fma2(ACC[3][2], A3, BB.x); fma2(ACC[3][3], A3, BB.y);

// ============================================================================
// Kernel 1: projection. grid (512, 3): x=64-row tile, y = {K, Q, V}.
// A: xs float[64][68]; B: ws2 u64[32][66] (pairs over k).
// wy==0 writes K transposed into g_kT; wy==1 writes Q scaled by QSC.
// ============================================================================
__global__ void __launch_bounds__(256)
proj_kernel(const float* __restrict__ x,
            const float* __restrict__ Wk,
            const float* __restrict__ Wq,
            const float* __restrict__ Wv) {
    __shared__ __align__(16) float xs[64 * 68];
    __shared__ __align__(16) u64   ws2[32 * 66];

    const int wy   = blockIdx.y;
    const float* W = (wy == 0) ? Wk : ((wy == 1) ? Wq : Wv);

    const int row0 = blockIdx.x * 64;
    const int tid  = threadIdx.x;
    const int tr4  = (tid >> 4) * 4;
    const int c0   = (tid & 15) * 2;   // owned cols: c0, c0+1, c0+32, c0+33

    u64 acc[4][4];
#pragma unroll
    for (int i = 0; i < 4; i++)
#pragma unroll
        for (int j = 0; j < 4; j++) acc[i][j] = 0ull;

    for (int kc = 0; kc < C_; kc += 64) {
#pragma unroll
        for (int i = 0; i < 4; i++) {
            int slot = i * 256 + tid;
            int r = slot >> 4;
            int c = (slot & 15) * 4;
            *(float4*)&xs[r * 68 + c] =
                *(const float4*)&x[(size_t)(row0 + r) * C_ + kc + c];
        }
#pragma unroll
        for (int i = 0; i < 2; i++) {
            int sp = i * 256 + tid;
            int kp = sp >> 4;
            int c  = (sp & 15) * 4;
            const float* wr = &W[(size_t)(kc + 2 * kp) * D_ + c];
            float4 wA = *(const float4*)wr;
            float4 wB = *(const float4*)(wr + D_);
            ulonglong2 p0 = { pk2(wA.x, wB.x), pk2(wA.y, wB.y) };
            ulonglong2 p1 = { pk2(wA.z, wB.z), pk2(wA.w, wB.w) };
            *(ulonglong2*)&ws2[kp * 66 + c]     = p0;
            *(ulonglong2*)&ws2[kp * 66 + c + 2] = p1;
        }
        __syncthreads();

#pragma unroll 4
        for (int kp2 = 0; kp2 < 16; kp2++) {
            const int fc = 4 * kp2;
            ulonglong2 a0 = *(const ulonglong2*)&xs[(tr4 + 0) * 68 + fc];
            ulonglong2 a1 = *(const ulonglong2*)&xs[(tr4 + 1) * 68 + fc];
            ulonglong2 a2 = *(const ulonglong2*)&xs[(tr4 + 2) * 68 + fc];
            ulonglong2 a3 = *(const ulonglong2*)&xs[(tr4 + 3) * 68 + fc];
            ulonglong2 bA0 = *(const ulonglong2*)&ws2[(2 * kp2) * 66 + c0];
            ulonglong2 bB0 = *(const ulonglong2*)&ws2[(2 * kp2) * 66 + 32 + c0];
            ulonglong2 bA1 = *(const ulonglong2*)&ws2[(2 * kp2 + 1) * 66 + c0];
            ulonglong2 bB1 = *(const ulonglong2*)&ws2[(2 * kp2 + 1) * 66 + 32 + c0];
            FMA_BLOCK(acc, a0.x, a1.x, a2.x, a3.x, bA0, bB0)
            FMA_BLOCK(acc, a0.y, a1.y, a2.y, a3.y, bA1, bB1)
        }
        __syncthreads();
    }

    if (wy == 0) {
        // K: transposed write g_kT[col][row0+tr4 .. +3].
#pragma unroll
        for (int j = 0; j < 4; j++) {
            int col = (j < 2) ? (c0 + j) : (32 + c0 + (j - 2));
            float4 v = { sum2(acc[0][j]), sum2(acc[1][j]),
                         sum2(acc[2][j]), sum2(acc[3][j]) };
            *(float4*)&g_kT[(size_t)col * BT_ + row0 + tr4] = v;
        }
    } else {
        float* out = (wy == 1) ? g_q : g_v;
        const float sc = (wy == 1) ? QSC : 1.0f;
#pragma unroll
        for (int i = 0; i < 4; i++) {
            float* orow = &out[(size_t)(row0 + tr4 + i) * D_];
            float2 r01 = { sum2(acc[i][0]) * sc, sum2(acc[i][1]) * sc };
            float2 r23 = { sum2(acc[i][2]) * sc, sum2(acc[i][3]) * sc };
            *(float2*)&orow[c0]      = r01;
            *(float2*)&orow[32 + c0] = r23;
        }
    }
}

// ============================================================================
// Kernel 2: flash attention.
// smem (floats): Qs[64*68] @0 | Ss[64*68] @4352 | Kt2 u64[32*66] @8704f |
//                Vs2 u64[32*66] @12928f.  Total 17152 floats = 68608 bytes.
// ============================================================================
#define ATTN_SMEM_BYTES (17152 * 4)

__global__ void __launch_bounds__(256, 2)
attn_kernel(float* __restrict__ out) {
    extern __shared__ __align__(16) float sm[];
    float* Qs  = sm;
    float* Ss  = sm + 4352;
    u64*   Kt2 = (u64*)(sm + 8704);
    u64*   Vs2 = (u64*)(sm + 12928);

    const int bid = blockIdx.x;
    const int qt  = 63 - (bid >> 3);   // heaviest query tiles first
    const int b   = bid & 7;
    const int q0  = qt * 64;
    const int tid = threadIdx.x;
    const int tr4 = (tid >> 4) * 4;
    const int c0  = (tid & 15) * 2;

    // Q tile (already scaled by proj), row-major stride 68.
#pragma unroll
    for (int i = 0; i < 4; i++) {
        int slot = i * 256 + tid;
        int r = slot >> 4;
        int c = (slot & 15) * 4;
        *(float4*)&Qs[r * 68 + c] =
            *(const float4*)&g_q[((size_t)b * T_ + q0 + r) * D_ + c];
    }

    float m[4], l[4];
#pragma unroll
    for (int i = 0; i < 4; i++) { m[i] = -CUDART_INF_F; l[i] = 0.0f; }

    u64 o2[4][4];
#pragma unroll
    for (int i = 0; i < 4; i++)
#pragma unroll
        for (int j = 0; j < 4; j++) o2[i][j] = 0ull;

    for (int kt = 0; kt <= qt; kt++) {
        const int k0 = kt * 64;

        // K fill from g_kT: coalesced loads, pair-pack over d, floor stores.
#pragma unroll
        for (int i = 0; i < 2; i++) {
            int slot = i * 256 + tid;
            int kp = slot >> 4;            // d-pair 0..31
            int ky = (slot & 15) * 4;      // key quad
            const float* r0p = &g_kT[(size_t)(2 * kp) * BT_ + b * T_ + k0 + ky];
            float4 fa = *(const float4*)r0p;
            float4 fb = *(const float4*)(r0p + BT_);
            ulonglong2 p0 = { pk2(fa.x, fb.x), pk2(fa.y, fb.y) };
            ulonglong2 p1 = { pk2(fa.z, fb.z), pk2(fa.w, fb.w) };
            *(ulonglong2*)&Kt2[kp * 66 + ky]     = p0;
            *(ulonglong2*)&Kt2[kp * 66 + ky + 2] = p1;
        }
        // V fill: pairs over key dim.
#pragma unroll
        for (int i = 0; i < 2; i++) {
            int sp = i * 256 + tid;
            int keyp = sp >> 4;
            int c = (sp & 15) * 4;
            const float* vr = &g_v[((size_t)b * T_ + k0 + 2 * keyp) * D_ + c];
            float4 vA = *(const float4*)vr;
            float4 vB = *(const float4*)(vr + D_);
            ulonglong2 p0 = { pk2(vA.x, vB.x), pk2(vA.y, vB.y) };
            ulonglong2 p1 = { pk2(vA.z, vB.z), pk2(vA.w, vB.w) };
            *(ulonglong2*)&Vs2[keyp * 66 + c]     = p0;
            *(ulonglong2*)&Vs2[keyp * 66 + c + 2] = p1;
        }
        __syncthreads();   // A: K/V (and Q first iter) visible

        // ---- S = Q @ K^T ----
        u64 acc[4][4];
#pragma unroll
        for (int i = 0; i < 4; i++)
#pragma unroll
            for (int j = 0; j < 4; j++) acc[i][j] = 0ull;

#pragma unroll 4
        for (int kp2 = 0; kp2 < 16; kp2++) {
            const int fc = 4 * kp2;
            ulonglong2 a0 = *(const ulonglong2*)&Qs[(tr4 + 0) * 68 + fc];
            ulonglong2 a1 = *(const ulonglong2*)&Qs[(tr4 + 1) * 68 + fc];
            ulonglong2 a2 = *(const ulonglong2*)&Qs[(tr4 + 2) * 68 + fc];
            ulonglong2 a3 = *(const ulonglong2*)&Qs[(tr4 + 3) * 68 + fc];
            ulonglong2 bA0 = *(const ulonglong2*)&Kt2[(2 * kp2) * 66 + c0];
            ulonglong2 bB0 = *(const ulonglong2*)&Kt2[(2 * kp2) * 66 + 32 + c0];
            ulonglong2 bA1 = *(const ulonglong2*)&Kt2[(2 * kp2 + 1) * 66 + c0];
            ulonglong2 bB1 = *(const ulonglong2*)&Kt2[(2 * kp2 + 1) * 66 + 32 + c0];
            FMA_BLOCK(acc, a0.x, a1.x, a2.x, a3.x, bA0, bB0)
            FMA_BLOCK(acc, a0.y, a1.y, a2.y, a3.y, bA1, bB1)
        }

        // ---- In-register online softmax ----
        float s[4][4];
#pragma unroll
        for (int i = 0; i < 4; i++) {
            s[i][0] = sum2(acc[i][0]);
            s[i][1] = sum2(acc[i][1]);
            s[i][2] = sum2(acc[i][2]);
            s[i][3] = sum2(acc[i][3]);
        }
        if (kt == qt) {
#pragma unroll
            for (int i = 0; i < 4; i++) {
                int row = tr4 + i;
                if (c0 + 0  > row) s[i][0] = -CUDART_INF_F;
                if (c0 + 1  > row) s[i][1] = -CUDART_INF_F;
                if (c0 + 32 > row) s[i][2] = -CUDART_INF_F;
                if (c0 + 33 > row) s[i][3] = -CUDART_INF_F;
            }
        }
#pragma unroll
        for (int i = 0; i < 4; i++) {
            float mx = fmaxf(fmaxf(s[i][0], s[i][1]), fmaxf(s[i][2], s[i][3]));
            mx = fmaxf(mx, __shfl_xor_sync(0xffffffffu, mx, 1));
            mx = fmaxf(mx, __shfl_xor_sync(0xffffffffu, mx, 2));
            mx = fmaxf(mx, __shfl_xor_sync(0xffffffffu, mx, 4));
            mx = fmaxf(mx, __shfl_xor_sync(0xffffffffu, mx, 8));

            float m_new = fmaxf(m[i], mx);
            float alpha = ex2(m[i] - m_new);   // exp2(-inf)=0 on first tile
            m[i] = m_new;

            float p0 = ex2(s[i][0] - m_new);
            float p1 = ex2(s[i][1] - m_new);
            float p2 = ex2(s[i][2] - m_new);
            float p3 = ex2(s[i][3] - m_new);
            float ps = (p0 + p1) + (p2 + p3);
            ps += __shfl_xor_sync(0xffffffffu, ps, 1);
            ps += __shfl_xor_sync(0xffffffffu, ps, 2);
            ps += __shfl_xor_sync(0xffffffffu, ps, 4);
            ps += __shfl_xor_sync(0xffffffffu, ps, 8);
            l[i] = l[i] * alpha + ps;

            u64 al2 = pk2(alpha, alpha);
            o2[i][0] = mul2(o2[i][0], al2);
            o2[i][1] = mul2(o2[i][1], al2);
            o2[i][2] = mul2(o2[i][2], al2);
            o2[i][3] = mul2(o2[i][3], al2);

            int row = tr4 + i;
            float2 w01 = { p0, p1 };
            float2 w23 = { p2, p3 };
            *(float2*)&Ss[row * 68 + c0]      = w01;
            *(float2*)&Ss[row * 68 + 32 + c0] = w23;
        }
        __syncthreads();   // B: P visible

        // ---- O += P @ V ----
#pragma unroll 4
        for (int kp2 = 0; kp2 < 16; kp2++) {
            const int fc = 4 * kp2;
            ulonglong2 a0 = *(const ulonglong2*)&Ss[(tr4 + 0) * 68 + fc];
            ulonglong2 a1 = *(const ulonglong2*)&Ss[(tr4 + 1) * 68 + fc];
            ulonglong2 a2 = *(const ulonglong2*)&Ss[(tr4 + 2) * 68 + fc];
            ulonglong2 a3 = *(const ulonglong2*)&Ss[(tr4 + 3) * 68 + fc];
            ulonglong2 bA0 = *(const ulonglong2*)&Vs2[(2 * kp2) * 66 + c0];
            ulonglong2 bB0 = *(const ulonglong2*)&Vs2[(2 * kp2) * 66 + 32 + c0];
            ulonglong2 bA1 = *(const ulonglong2*)&Vs2[(2 * kp2 + 1) * 66 + c0];
            ulonglong2 bB1 = *(const ulonglong2*)&Vs2[(2 * kp2 + 1) * 66 + 32 + c0];
            FMA_BLOCK(o2, a0.x, a1.x, a2.x, a3.x, bA0, bB0)
            FMA_BLOCK(o2, a0.y, a1.y, a2.y, a3.y, bA1, bB1)
        }
        __syncthreads();   // C: tiles reusable
    }

    // Epilogue: normalize and store.
#pragma unroll
    for (int i = 0; i < 4; i++) {
        float linv = 1.0f / l[i];
        float* orow = &out[((size_t)b * T_ + q0 + tr4 + i) * D_];
        float2 r01 = { sum2(o2[i][0]) * linv, sum2(o2[i][1]) * linv };
        float2 r23 = { sum2(o2[i][2]) * linv, sum2(o2[i][3]) * linv };
        *(float2*)&orow[c0]      = r01;
        *(float2*)&orow[32 + c0] = r23;
    }
}

// ============================================================================
extern "C" void kernel_launch(void* const* d_in, const int* in_sizes, int n_in,
                              void* d_out, int out_size) {
    const float* x  = (const float*)d_in[0];
    const float* Wk = (const float*)d_in[1];
    const float* Wq = (const float*)d_in[2];
    const float* Wv = (const float*)d_in[3];
    float* out = (float*)d_out;
    (void)in_sizes; (void)n_in; (void)out_size;

    cudaFuncSetAttribute(attn_kernel,
                         cudaFuncAttributeMaxDynamicSharedMemorySize,
                         ATTN_SMEM_BYTES);

    proj_kernel<<<dim3(BT_ / 64, 3), 256>>>(x, Wk, Wq, Wv);
    attn_kernel<<<B_ * (T_ / 64), 256, ATTN_SMEM_BYTES>>>(out);
}

// round 8
// speedup vs baseline: 1.3055x; 1.0005x over previous
#include <cuda_runtime.h>
#include <cuda_bf16.h>
#include <math_constants.h>

// ============================================================================
// Head: single-head causal attention. B=8, T=4096, C=768, D=64, fp32.
// Round 6 = Round 5 resubmit (infra failure, no measurement taken).
//  - A tiles (Qs/Ss/xs) padded to stride 68 floats -> conflict-free broadcast.
//  - A loaded as LDS.128 spanning 2 k-pairs (bitwise f32x2 pairs).
//  - K written TRANSPOSED by proj (g_kT[d][b*T+t]) so attn's K-fill is
//    coalesced loads + floor-rate ulonglong2 stores (no 4-phase transpose).
//  - QSC (scale*log2e) folded into proj's Q output.
// ============================================================================

#define B_   8
#define T_   4096
#define C_   768
#define D_   64
#define BT_  (B_ * T_)
#define QSC  0.18033688011112042591f

typedef unsigned long long u64;

__device__ __forceinline__ u64 pk2(float lo, float hi) {
    u64 r; asm("mov.b64 %0, {%1, %2};" : "=l"(r) : "f"(lo), "f"(hi)); return r;
}
__device__ __forceinline__ void fma2(u64& d, u64 a, u64 b) {
    asm("fma.rn.f32x2 %0, %1, %2, %0;" : "+l"(d) : "l"(a), "l"(b));
}
__device__ __forceinline__ u64 mul2(u64 a, u64 b) {
    u64 d; asm("mul.rn.f32x2 %0, %1, %2;" : "=l"(d) : "l"(a), "l"(b)); return d;
}
__device__ __forceinline__ float sum2(u64 v) {
    float lo, hi;
    asm("mov.b64 {%0, %1}, %2;" : "=f"(lo), "=f"(hi) : "l"(v));
    return lo + hi;
}
__device__ __forceinline__ float ex2(float x) {
    float r; asm("ex2.approx.f32 %0, %1;" : "=f"(r) : "f"(x)); return r;
}

// Scratch (static; no allocations). q: pre-scaled by QSC. kT: [d][b*T+t].
__device__ __align__(16) float g_q [BT_ * D_];
__device__ __align__(16) float g_kT[D_ * BT_];
__device__ __align__(16) float g_v [BT_ * D_];

// 16 FFMA2: one k-pair across the thread's 4x4 output subtile.
#define FMA_BLOCK(ACC, A0, A1, A2, A3, BA, BB)                                 \
    fma2(ACC[0][0], A0, BA.x); fma2(ACC[0][1], A0, BA.y);                      \
    fma2(ACC[0][2], A0, BB.x); fma2(ACC[0][3], A0, BB.y);                      \
    fma2(ACC[1][0], A1, BA.x); fma2(ACC[1][1], A1, BA.y);                      \
    fma2(ACC[1][2], A1, BB.x); fma2(ACC[1][3], A1, BB.y);                      \
    fma2(ACC[2][0], A2, BA.x); fma2(ACC[2][1], A2, BA.y);                      \
    fma2(ACC[2][2], A2, BB.x); fma2(ACC[2][3], A2, BB.y);                      \
    fma2(ACC[3][0], A3, BA.x); fma2(ACC[3][1], A3, BA.y);                      \
    fma2(ACC[3][2], A3, BB.x); fma2(ACC[3][3], A3, BB.y);

// ============================================================================
// Kernel 1: projection. grid (512, 3): x=64-row tile, y = {K, Q, V}.
// A: xs float[64][68]; B: ws2 u64[32][66] (pairs over k).
// wy==0 writes K transposed into g_kT; wy==1 writes Q scaled by QSC.
// ============================================================================
__global__ void __launch_bounds__(256)
proj_kernel(const float* __restrict__ x,
            const float* __restrict__ Wk,
            const float* __restrict__ Wq,
            const float* __restrict__ Wv) {
    __shared__ __align__(16) float xs[64 * 68];
    __shared__ __align__(16) u64   ws2[32 * 66];

    const int wy   = blockIdx.y;
    const float* W = (wy == 0) ? Wk : ((wy == 1) ? Wq : Wv);

    const int row0 = blockIdx.x * 64;
    const int tid  = threadIdx.x;
    const int tr4  = (tid >> 4) * 4;
    const int c0   = (tid & 15) * 2;   // owned cols: c0, c0+1, c0+32, c0+33

    u64 acc[4][4];
#pragma unroll
    for (int i = 0; i < 4; i++)
#pragma unroll
        for (int j = 0; j < 4; j++) acc[i][j] = 0ull;

    for (int kc = 0; kc < C_; kc += 64) {
#pragma unroll
        for (int i = 0; i < 4; i++) {
            int slot = i * 256 + tid;
            int r = slot >> 4;
            int c = (slot & 15) * 4;
            *(float4*)&xs[r * 68 + c] =
                *(const float4*)&x[(size_t)(row0 + r) * C_ + kc + c];
        }
#pragma unroll
        for (int i = 0; i < 2; i++) {
            int sp = i * 256 + tid;
            int kp = sp >> 4;
            int c  = (sp & 15) * 4;
            const float* wr = &W[(size_t)(kc + 2 * kp) * D_ + c];
            float4 wA = *(const float4*)wr;
            float4 wB = *(const float4*)(wr + D_);
            ulonglong2 p0 = { pk2(wA.x, wB.x), pk2(wA.y, wB.y) };
            ulonglong2 p1 = { pk2(wA.z, wB.z), pk2(wA.w, wB.w) };
            *(ulonglong2*)&ws2[kp * 66 + c]     = p0;
            *(ulonglong2*)&ws2[kp * 66 + c + 2] = p1;
        }
        __syncthreads();

#pragma unroll 4
        for (int kp2 = 0; kp2 < 16; kp2++) {
            const int fc = 4 * kp2;
            ulonglong2 a0 = *(const ulonglong2*)&xs[(tr4 + 0) * 68 + fc];
            ulonglong2 a1 = *(const ulonglong2*)&xs[(tr4 + 1) * 68 + fc];
            ulonglong2 a2 = *(const ulonglong2*)&xs[(tr4 + 2) * 68 + fc];
            ulonglong2 a3 = *(const ulonglong2*)&xs[(tr4 + 3) * 68 + fc];
            ulonglong2 bA0 = *(const ulonglong2*)&ws2[(2 * kp2) * 66 + c0];
            ulonglong2 bB0 = *(const ulonglong2*)&ws2[(2 * kp2) * 66 + 32 + c0];
            ulonglong2 bA1 = *(const ulonglong2*)&ws2[(2 * kp2 + 1) * 66 + c0];
            ulonglong2 bB1 = *(const ulonglong2*)&ws2[(2 * kp2 + 1) * 66 + 32 + c0];
            FMA_BLOCK(acc, a0.x, a1.x, a2.x, a3.x, bA0, bB0)
            FMA_BLOCK(acc, a0.y, a1.y, a2.y, a3.y, bA1, bB1)
        }
        __syncthreads();
    }

    if (wy == 0) {
        // K: transposed write g_kT[col][row0+tr4 .. +3].
#pragma unroll
        for (int j = 0; j < 4; j++) {
            int col = (j < 2) ? (c0 + j) : (32 + c0 + (j - 2));
            float4 v = { sum2(acc[0][j]), sum2(acc[1][j]),
                         sum2(acc[2][j]), sum2(acc[3][j]) };
            *(float4*)&g_kT[(size_t)col * BT_ + row0 + tr4] = v;
        }
    } else {
        float* out = (wy == 1) ? g_q : g_v;
        const float sc = (wy == 1) ? QSC : 1.0f;
#pragma unroll
        for (int i = 0; i < 4; i++) {
            float* orow = &out[(size_t)(row0 + tr4 + i) * D_];
            float2 r01 = { sum2(acc[i][0]) * sc, sum2(acc[i][1]) * sc };
            float2 r23 = { sum2(acc[i][2]) * sc, sum2(acc[i][3]) * sc };
            *(float2*)&orow[c0]      = r01;
            *(float2*)&orow[32 + c0] = r23;
        }
    }
}

// ============================================================================
// Kernel 2: flash attention.
// smem (floats): Qs[64*68] @0 | Ss[64*68] @4352 | Kt2 u64[32*66] @8704f |
//                Vs2 u64[32*66] @12928f.  Total 17152 floats = 68608 bytes.
// ============================================================================
#define ATTN_SMEM_BYTES (17152 * 4)

__global__ void __launch_bounds__(256, 2)
attn_kernel(float* __restrict__ out) {
    extern __shared__ __align__(16) float sm[];
    float* Qs  = sm;
    float* Ss  = sm + 4352;
    u64*   Kt2 = (u64*)(sm + 8704);
    u64*   Vs2 = (u64*)(sm + 12928);

    const int bid = blockIdx.x;
    const int qt  = 63 - (bid >> 3);   // heaviest query tiles first
    const int b   = bid & 7;
    const int q0  = qt * 64;
    const int tid = threadIdx.x;
    const int tr4 = (tid >> 4) * 4;
    const int c0  = (tid & 15) * 2;

    // Q tile (already scaled by proj), row-major stride 68.
#pragma unroll
    for (int i = 0; i < 4; i++) {
        int slot = i * 256 + tid;
        int r = slot >> 4;
        int c = (slot & 15) * 4;
        *(float4*)&Qs[r * 68 + c] =
            *(const float4*)&g_q[((size_t)b * T_ + q0 + r) * D_ + c];
    }

    float m[4], l[4];
#pragma unroll
    for (int i = 0; i < 4; i++) { m[i] = -CUDART_INF_F; l[i] = 0.0f; }

    u64 o2[4][4];
#pragma unroll
    for (int i = 0; i < 4; i++)
#pragma unroll
        for (int j = 0; j < 4; j++) o2[i][j] = 0ull;

    for (int kt = 0; kt <= qt; kt++) {
        const int k0 = kt * 64;

        // K fill from g_kT: coalesced loads, pair-pack over d, floor stores.
#pragma unroll
        for (int i = 0; i < 2; i++) {
            int slot = i * 256 + tid;
            int kp = slot >> 4;            // d-pair 0..31
            int ky = (slot & 15) * 4;      // key quad
            const float* r0p = &g_kT[(size_t)(2 * kp) * BT_ + b * T_ + k0 + ky];
            float4 fa = *(const float4*)r0p;
            float4 fb = *(const float4*)(r0p + BT_);
            ulonglong2 p0 = { pk2(fa.x, fb.x), pk2(fa.y, fb.y) };
            ulonglong2 p1 = { pk2(fa.z, fb.z), pk2(fa.w, fb.w) };
            *(ulonglong2*)&Kt2[kp * 66 + ky]     = p0;
            *(ulonglong2*)&Kt2[kp * 66 + ky + 2] = p1;
        }
        // V fill: pairs over key dim.
#pragma unroll
        for (int i = 0; i < 2; i++) {
            int sp = i * 256 + tid;
            int keyp = sp >> 4;
            int c = (sp & 15) * 4;
            const float* vr = &g_v[((size_t)b * T_ + k0 + 2 * keyp) * D_ + c];
            float4 vA = *(const float4*)vr;
            float4 vB = *(const float4*)(vr + D_);
            ulonglong2 p0 = { pk2(vA.x, vB.x), pk2(vA.y, vB.y) };
            ulonglong2 p1 = { pk2(vA.z, vB.z), pk2(vA.w, vB.w) };
            *(ulonglong2*)&Vs2[keyp * 66 + c]     = p0;
            *(ulonglong2*)&Vs2[keyp * 66 + c + 2] = p1;
        }
        __syncthreads();   // A: K/V (and Q first iter) visible

        // ---- S = Q @ K^T ----
        u64 acc[4][4];
#pragma unroll
        for (int i = 0; i < 4; i++)
#pragma unroll
            for (int j = 0; j < 4; j++) acc[i][j] = 0ull;

#pragma unroll 4
        for (int kp2 = 0; kp2 < 16; kp2++) {
            const int fc = 4 * kp2;
            ulonglong2 a0 = *(const ulonglong2*)&Qs[(tr4 + 0) * 68 + fc];
            ulonglong2 a1 = *(const ulonglong2*)&Qs[(tr4 + 1) * 68 + fc];
            ulonglong2 a2 = *(const ulonglong2*)&Qs[(tr4 + 2) * 68 + fc];
            ulonglong2 a3 = *(const ulonglong2*)&Qs[(tr4 + 3) * 68 + fc];
            ulonglong2 bA0 = *(const ulonglong2*)&Kt2[(2 * kp2) * 66 + c0];
            ulonglong2 bB0 = *(const ulonglong2*)&Kt2[(2 * kp2) * 66 + 32 + c0];
            ulonglong2 bA1 = *(const ulonglong2*)&Kt2[(2 * kp2 + 1) * 66 + c0];
            ulonglong2 bB1 = *(const ulonglong2*)&Kt2[(2 * kp2 + 1) * 66 + 32 + c0];
            FMA_BLOCK(acc, a0.x, a1.x, a2.x, a3.x, bA0, bB0)
            FMA_BLOCK(acc, a0.y, a1.y, a2.y, a3.y, bA1, bB1)
        }

        // ---- In-register online softmax ----
        float s[4][4];
#pragma unroll
        for (int i = 0; i < 4; i++) {
            s[i][0] = sum2(acc[i][0]);
            s[i][1] = sum2(acc[i][1]);
            s[i][2] = sum2(acc[i][2]);
            s[i][3] = sum2(acc[i][3]);
        }
        if (kt == qt) {
#pragma unroll
            for (int i = 0; i < 4; i++) {
                int row = tr4 + i;
                if (c0 + 0  > row) s[i][0] = -CUDART_INF_F;
                if (c0 + 1  > row) s[i][1] = -CUDART_INF_F;
                if (c0 + 32 > row) s[i][2] = -CUDART_INF_F;
                if (c0 + 33 > row) s[i][3] = -CUDART_INF_F;
            }
        }
#pragma unroll
        for (int i = 0; i < 4; i++) {
            float mx = fmaxf(fmaxf(s[i][0], s[i][1]), fmaxf(s[i][2], s[i][3]));
            mx = fmaxf(mx, __shfl_xor_sync(0xffffffffu, mx, 1));
            mx = fmaxf(mx, __shfl_xor_sync(0xffffffffu, mx, 2));
            mx = fmaxf(mx, __shfl_xor_sync(0xffffffffu, mx, 4));
            mx = fmaxf(mx, __shfl_xor_sync(0xffffffffu, mx, 8));

            float m_new = fmaxf(m[i], mx);
            float alpha = ex2(m[i] - m_new);   // exp2(-inf)=0 on first tile
            m[i] = m_new;

            float p0 = ex2(s[i][0] - m_new);
            float p1 = ex2(s[i][1] - m_new);
            float p2 = ex2(s[i][2] - m_new);
            float p3 = ex2(s[i][3] - m_new);
            float ps = (p0 + p1) + (p2 + p3);
            ps += __shfl_xor_sync(0xffffffffu, ps, 1);
            ps += __shfl_xor_sync(0xffffffffu, ps, 2);
            ps += __shfl_xor_sync(0xffffffffu, ps, 4);
            ps += __shfl_xor_sync(0xffffffffu, ps, 8);
            l[i] = l[i] * alpha + ps;

            u64 al2 = pk2(alpha, alpha);
            o2[i][0] = mul2(o2[i][0], al2);
            o2[i][1] = mul2(o2[i][1], al2);
            o2[i][2] = mul2(o2[i][2], al2);
            o2[i][3] = mul2(o2[i][3], al2);

            int row = tr4 + i;
            float2 w01 = { p0, p1 };
            float2 w23 = { p2, p3 };
            *(float2*)&Ss[row * 68 + c0]      = w01;
            *(float2*)&Ss[row * 68 + 32 + c0] = w23;
        }
        __syncthreads();   // B: P visible

        // ---- O += P @ V ----
#pragma unroll 4
        for (int kp2 = 0; kp2 < 16; kp2++) {
            const int fc = 4 * kp2;
            ulonglong2 a0 = *(const ulonglong2*)&Ss[(tr4 + 0) * 68 + fc];
            ulonglong2 a1 = *(const ulonglong2*)&Ss[(tr4 + 1) * 68 + fc];
            ulonglong2 a2 = *(const ulonglong2*)&Ss[(tr4 + 2) * 68 + fc];
            ulonglong2 a3 = *(const ulonglong2*)&Ss[(tr4 + 3) * 68 + fc];
            ulonglong2 bA0 = *(const ulonglong2*)&Vs2[(2 * kp2) * 66 + c0];
            ulonglong2 bB0 = *(const ulonglong2*)&Vs2[(2 * kp2) * 66 + 32 + c0];
            ulonglong2 bA1 = *(const ulonglong2*)&Vs2[(2 * kp2 + 1) * 66 + c0];
            ulonglong2 bB1 = *(const ulonglong2*)&Vs2[(2 * kp2 + 1) * 66 + 32 + c0];
            FMA_BLOCK(o2, a0.x, a1.x, a2.x, a3.x, bA0, bB0)
            FMA_BLOCK(o2, a0.y, a1.y, a2.y, a3.y, bA1, bB1)
        }
        __syncthreads();   // C: tiles reusable
    }

    // Epilogue: normalize and store.
#pragma unroll
    for (int i = 0; i < 4; i++) {
        float linv = 1.0f / l[i];
        float* orow = &out[((size_t)b * T_ + q0 + tr4 + i) * D_];
        float2 r01 = { sum2(o2[i][0]) * linv, sum2(o2[i][1]) * linv };
        float2 r23 = { sum2(o2[i][2]) * linv, sum2(o2[i][3]) * linv };
        *(float2*)&orow[c0]      = r01;
        *(float2*)&orow[32 + c0] = r23;
    }
}

// ============================================================================
extern "C" void kernel_launch(void* const* d_in, const int* in_sizes, int n_in,
                              void* d_out, int out_size) {
    const float* x  = (const float*)d_in[0];
    const float* Wk = (const float*)d_in[1];
    const float* Wq = (const float*)d_in[2];
    const float* Wv = (const float*)d_in[3];
    float* out = (float*)d_out;
    (void)in_sizes; (void)n_in; (void)out_size;

    cudaFuncSetAttribute(attn_kernel,
                         cudaFuncAttributeMaxDynamicSharedMemorySize,
                         ATTN_SMEM_BYTES);

    proj_kernel<<<dim3(BT_ / 64, 3), 256>>>(x, Wk, Wq, Wv);
    attn_kernel<<<B_ * (T_ / 64), 256, ATTN_SMEM_BYTES>>>(out);
}

// round 12
// speedup vs baseline: 1.8144x; 1.3898x over previous
#include <cuda_runtime.h>
#include <cuda_bf16.h>
#include <math_constants.h>
#include <cstdint>

// ============================================================================
// Head: single-head causal attention. B=8, T=4096, C=768, D=64, fp32.
// Round 10: R9 design with the fill_tile store-stride bug fixed (8*j, not
// 16*j — bf16 bytes, not fp32 bytes; the 16*j version overflowed each smem
// region and the dynamic smem allocation -> illegal memory access).
// Tensor path: arch-agnostic mma.sync.m16n8k16 bf16x3 + ldmatrix; no-max
// base-2 softmax; O in registers; P repacked C-frag -> A-frag in registers.
// ============================================================================

#define B_   8
#define T_   4096
#define C_   768
#define D_   64
#define BT_  (B_ * T_)
#define QSC  0.18033688011112042591f   // (1/sqrt(64)) * log2(e)

#define TQ 128      // queries per CTA
#define TK 128      // keys per kv tile
#define PITCH 72    // halves per smem row (144 B -> ldmatrix conflict-free)

typedef unsigned long long u64;

// ---------------- scratch (static, no allocations) ----------------
__device__ __align__(16) float g_q[BT_ * D_];   // pre-scaled by QSC
__device__ __align__(16) float g_k[BT_ * D_];
__device__ __align__(16) float g_v[BT_ * D_];

// ---------------- helpers ----------------
__device__ __forceinline__ uint32_t smem_u32(const void* p) {
    uint32_t a;
    asm("{ .reg .u64 t; cvta.to.shared.u64 t, %1; cvt.u32.u64 %0, t; }"
        : "=r"(a) : "l"(p));
    return a;
}
__device__ __forceinline__ float ex2(float x) {
    float r; asm("ex2.approx.f32 %0, %1;" : "=f"(r) : "f"(x)); return r;
}
__device__ __forceinline__ u64 pk2(float lo, float hi) {
    u64 r; asm("mov.b64 %0, {%1, %2};" : "=l"(r) : "f"(lo), "f"(hi)); return r;
}
__device__ __forceinline__ void fma2(u64& d, u64 a, u64 b) {
    asm("fma.rn.f32x2 %0, %1, %2, %0;" : "+l"(d) : "l"(a), "l"(b));
}
__device__ __forceinline__ float sum2(u64 v) {
    float lo, hi;
    asm("mov.b64 {%0, %1}, %2;" : "=f"(lo), "=f"(hi) : "l"(v));
    return lo + hi;
}
// fp32 pair -> bf16 hi pair + bf16 residual pair (packed half2 words).
__device__ __forceinline__ void split2(float a, float b, uint32_t& hi, uint32_t& lo) {
    __nv_bfloat162 h = __floats2bfloat162_rn(a, b);
    float2 hf = __bfloat1622float2(h);
    __nv_bfloat162 l2 = __floats2bfloat162_rn(a - hf.x, b - hf.y);
    hi = *(uint32_t*)&h;
    lo = *(uint32_t*)&l2;
}

__device__ __forceinline__ void ldsm_x4(uint32_t* r, uint32_t addr) {
    asm volatile("ldmatrix.sync.aligned.m8n8.x4.shared.b16 {%0,%1,%2,%3}, [%4];"
                 : "=r"(r[0]), "=r"(r[1]), "=r"(r[2]), "=r"(r[3]) : "r"(addr));
}
__device__ __forceinline__ void ldsm_x4_t(uint32_t* r, uint32_t addr) {
    asm volatile("ldmatrix.sync.aligned.m8n8.x4.trans.shared.b16 {%0,%1,%2,%3}, [%4];"
                 : "=r"(r[0]), "=r"(r[1]), "=r"(r[2]), "=r"(r[3]) : "r"(addr));
}
__device__ __forceinline__ void mma16816(float* c, const uint32_t* a,
                                         uint32_t b0, uint32_t b1) {
    asm volatile(
        "mma.sync.aligned.m16n8k16.row.col.f32.bf16.bf16.f32 "
        "{%0,%1,%2,%3}, {%4,%5,%6,%7}, {%8,%9}, {%0,%1,%2,%3};"
        : "+f"(c[0]), "+f"(c[1]), "+f"(c[2]), "+f"(c[3])
        : "r"(a[0]), "r"(a[1]), "r"(a[2]), "r"(a[3]), "r"(b0), "r"(b1));
}

// ============================================================================
// Kernel 1: projection (FFMA2, measured). Q pre-scaled by QSC; K, V natural.
// ============================================================================
#define FMA_BLOCK(ACC, A0, A1, A2, A3, BA, BB)                                 \
    fma2(ACC[0][0], A0, BA.x); fma2(ACC[0][1], A0, BA.y);                      \
    fma2(ACC[0][2], A0, BB.x); fma2(ACC[0][3], A0, BB.y);                      \
    fma2(ACC[1][0], A1, BA.x); fma2(ACC[1][1], A1, BA.y);                      \
    fma2(ACC[1][2], A1, BB.x); fma2(ACC[1][3], A1, BB.y);                      \
    fma2(ACC[2][0], A2, BA.x); fma2(ACC[2][1], A2, BA.y);                      \
    fma2(ACC[2][2], A2, BB.x); fma2(ACC[2][3], A2, BB.y);                      \
    fma2(ACC[3][0], A3, BA.x); fma2(ACC[3][1], A3, BA.y);                      \
    fma2(ACC[3][2], A3, BB.x); fma2(ACC[3][3], A3, BB.y);

__global__ void __launch_bounds__(256)
proj_kernel(const float* __restrict__ x,
            const float* __restrict__ Wk,
            const float* __restrict__ Wq,
            const float* __restrict__ Wv) {
    __shared__ __align__(16) float xs[64 * 68];
    __shared__ __align__(16) u64   ws2[32 * 66];

    const int wy   = blockIdx.y;
    const float* W = (wy == 0) ? Wk : ((wy == 1) ? Wq : Wv);
    float* out     = (wy == 0) ? g_k : ((wy == 1) ? g_q : g_v);
    const float sc = (wy == 1) ? QSC : 1.0f;

    const int row0 = blockIdx.x * 64;
    const int tid  = threadIdx.x;
    const int tr4  = (tid >> 4) * 4;
    const int c0   = (tid & 15) * 2;

    u64 acc[4][4];
#pragma unroll
    for (int i = 0; i < 4; i++)
#pragma unroll
        for (int j = 0; j < 4; j++) acc[i][j] = 0ull;

    for (int kc = 0; kc < C_; kc += 64) {
#pragma unroll
        for (int i = 0; i < 4; i++) {
            int slot = i * 256 + tid;
            int r = slot >> 4;
            int c = (slot & 15) * 4;
            *(float4*)&xs[r * 68 + c] =
                *(const float4*)&x[(size_t)(row0 + r) * C_ + kc + c];
        }
#pragma unroll
        for (int i = 0; i < 2; i++) {
            int sp = i * 256 + tid;
            int kp = sp >> 4;
            int c  = (sp & 15) * 4;
            const float* wr = &W[(size_t)(kc + 2 * kp) * D_ + c];
            float4 wA = *(const float4*)wr;
            float4 wB = *(const float4*)(wr + D_);
            ulonglong2 p0 = { pk2(wA.x, wB.x), pk2(wA.y, wB.y) };
            ulonglong2 p1 = { pk2(wA.z, wB.z), pk2(wA.w, wB.w) };
            *(ulonglong2*)&ws2[kp * 66 + c]     = p0;
            *(ulonglong2*)&ws2[kp * 66 + c + 2] = p1;
        }
        __syncthreads();

#pragma unroll 4
        for (int kp2 = 0; kp2 < 16; kp2++) {
            const int fc = 4 * kp2;
            ulonglong2 a0 = *(const ulonglong2*)&xs[(tr4 + 0) * 68 + fc];
            ulonglong2 a1 = *(const ulonglong2*)&xs[(tr4 + 1) * 68 + fc];
            ulonglong2 a2 = *(const ulonglong2*)&xs[(tr4 + 2) * 68 + fc];
            ulonglong2 a3 = *(const ulonglong2*)&xs[(tr4 + 3) * 68 + fc];
            ulonglong2 bA0 = *(const ulonglong2*)&ws2[(2 * kp2) * 66 + c0];
            ulonglong2 bB0 = *(const ulonglong2*)&ws2[(2 * kp2) * 66 + 32 + c0];
            ulonglong2 bA1 = *(const ulonglong2*)&ws2[(2 * kp2 + 1) * 66 + c0];
            ulonglong2 bB1 = *(const ulonglong2*)&ws2[(2 * kp2 + 1) * 66 + 32 + c0];
            FMA_BLOCK(acc, a0.x, a1.x, a2.x, a3.x, bA0, bB0)
            FMA_BLOCK(acc, a0.y, a1.y, a2.y, a3.y, bA1, bB1)
        }
        __syncthreads();
    }

#pragma unroll
    for (int i = 0; i < 4; i++) {
        float* orow = &out[(size_t)(row0 + tr4 + i) * D_];
        float2 r01 = { sum2(acc[i][0]) * sc, sum2(acc[i][1]) * sc };
        float2 r23 = { sum2(acc[i][2]) * sc, sum2(acc[i][3]) * sc };
        *(float2*)&orow[c0]      = r01;
        *(float2*)&orow[32 + c0] = r23;
    }
}

// ============================================================================
// Kernel 2: mma.sync flash attention (bf16x3, no-max softmax).
// grid = 256 (8 batches x 32 q-tiles of 128), block = 256 (8 warps x 16 rows).
// smem: Khi | Klo | Vhi | Vlo, each half[128][72]. Q aliases K region (used
// only before the kv loop).
// ============================================================================
#define SM_KHI  0
#define SM_KLO  18432
#define SM_VHI  36864
#define SM_VLO  55296
#define SM_ATTN 73728

// Fill one 128x64 fp32 tile into bf16 hi/lo smem arrays (256 threads).
// Each j handles 4 fp32 -> 4 bf16 halves = 8 BYTES per array (stride 8*j).
__device__ __forceinline__ void fill_tile(char* hi, char* lo,
                                          const float* __restrict__ g, int tid) {
    const int row = tid >> 1;
    const int d0  = (tid & 1) * 32;
    const float* gp = g + (size_t)row * D_ + d0;
    const int bo = (row * PITCH + d0) * 2;
#pragma unroll
    for (int j = 0; j < 8; j++) {
        float4 f = *(const float4*)(gp + 4 * j);
        uint32_t h0, l0, h1, l1;
        split2(f.x, f.y, h0, l0);
        split2(f.z, f.w, h1, l1);
        uint2 ph = { h0, h1 }, pl = { l0, l1 };
        *(uint2*)(hi + bo + 8 * j) = ph;
        *(uint2*)(lo + bo + 8 * j) = pl;
    }
}

__global__ void __launch_bounds__(256)
attn_mma(float* __restrict__ out) {
    extern __shared__ __align__(16) char sm[];
    const uint32_t smb = smem_u32(sm);

    const int tid  = threadIdx.x;
    const int lane = tid & 31;
    const int wid  = tid >> 5;
    const int bid  = blockIdx.x;
    const int qt   = 31 - (bid >> 3);    // heavy q-tiles first
    const int b    = bid & 7;
    const int q0   = qt * TQ;
    const int m0   = wid * 16;           // warp's query rows within tile

    // ---- Q tile -> smem (aliased on K region), then Q frags -> registers ----
    fill_tile(sm + SM_KHI, sm + SM_KLO, &g_q[((size_t)b * T_ + q0) * D_], tid);
    __syncthreads();

    uint32_t qhi[4][4], qlo[4][4];
    {
        const int r = m0 + (lane & 7) + ((lane >> 3) & 1) * 8;
        const int c = ((lane >> 4) & 1) * 8;
        const uint32_t a0 = smb + SM_KHI + (uint32_t)(r * PITCH + c) * 2;
        const uint32_t a1 = smb + SM_KLO + (uint32_t)(r * PITCH + c) * 2;
#pragma unroll
        for (int kk = 0; kk < 4; kk++) {
            ldsm_x4(qhi[kk], a0 + kk * 32);
            ldsm_x4(qlo[kk], a1 + kk * 32);
        }
    }
    __syncthreads();

    float o[8][4];
#pragma unroll
    for (int i = 0; i < 8; i++)
#pragma unroll
        for (int j = 0; j < 4; j++) o[i][j] = 0.0f;
    float lsum0 = 0.0f, lsum1 = 0.0f;

    const int lq  = lane >> 2;          // c-frag row within 8
    const int lc2 = 2 * (lane & 3);     // c-frag col pair within n8
    // ldmatrix lane-address components
    const int krow = (lane & 7) + ((lane >> 4) & 1) * 8;  // + ch*16
    const int kcol = ((lane >> 3) & 1) * 8;               // + kk*16
    const int vrow = (lane & 7) + ((lane >> 3) & 1) * 8;  // + ch*16
    const int vcol = (lane >> 4) * 8;                     // + dd*16

    for (int kt = 0; kt <= qt; kt++) {
        const int k0 = kt * TK;
        const bool diag = (kt == qt);

        fill_tile(sm + SM_KHI, sm + SM_KLO, &g_k[((size_t)b * T_ + k0) * D_], tid);
        fill_tile(sm + SM_VHI, sm + SM_VLO, &g_v[((size_t)b * T_ + k0) * D_], tid);
        __syncthreads();

        for (int ch = 0; ch < 8; ch++) {
            if (diag && ch * 16 > m0 + 15) break;   // fully-masked chunks

            // ---- S chunk = Q(16xd) K^T(16 keys): bf16x3, 24 MMAs ----
            float scf[8];
#pragma unroll
            for (int i = 0; i < 8; i++) scf[i] = 0.0f;
            {
                const uint32_t kh = smb + SM_KHI +
                    (uint32_t)((ch * 16 + krow) * PITCH + kcol) * 2;
                const uint32_t kl = smb + SM_KLO +
                    (uint32_t)((ch * 16 + krow) * PITCH + kcol) * 2;
#pragma unroll
                for (int kk = 0; kk < 4; kk++) {
                    uint32_t bh[4], bl[4];
                    ldsm_x4(bh, kh + kk * 32);
                    ldsm_x4(bl, kl + kk * 32);
                    mma16816(scf,     qhi[kk], bh[0], bh[1]);
                    mma16816(scf + 4, qhi[kk], bh[2], bh[3]);
                    mma16816(scf,     qhi[kk], bl[0], bl[1]);
                    mma16816(scf + 4, qhi[kk], bl[2], bl[3]);
                    mma16816(scf,     qlo[kk], bh[0], bh[1]);
                    mma16816(scf + 4, qlo[kk], bh[2], bh[3]);
                }
            }

            // ---- softmax (no max): p = exp2(s), causal mask on diagonal ----
            const int kb   = ch * 16 + lc2;
            const int lim0 = diag ? (m0 + lq)     : (1 << 30);
            const int lim1 = diag ? (m0 + lq + 8) : (1 << 30);
            float p0 = (kb     <= lim0) ? ex2(scf[0]) : 0.0f;
            float p1 = (kb + 1 <= lim0) ? ex2(scf[1]) : 0.0f;
            float p2 = (kb     <= lim1) ? ex2(scf[2]) : 0.0f;
            float p3 = (kb + 1 <= lim1) ? ex2(scf[3]) : 0.0f;
            float p4 = (kb + 8 <= lim0) ? ex2(scf[4]) : 0.0f;
            float p5 = (kb + 9 <= lim0) ? ex2(scf[5]) : 0.0f;
            float p6 = (kb + 8 <= lim1) ? ex2(scf[6]) : 0.0f;
            float p7 = (kb + 9 <= lim1) ? ex2(scf[7]) : 0.0f;
            lsum0 += (p0 + p1) + (p4 + p5);
            lsum1 += (p2 + p3) + (p6 + p7);

            // C-frag -> A-frag repack (registers only)
            uint32_t phi[4], plo[4];
            split2(p0, p1, phi[0], plo[0]);
            split2(p2, p3, phi[1], plo[1]);
            split2(p4, p5, phi[2], plo[2]);
            split2(p6, p7, phi[3], plo[3]);

            // ---- O += P(16x16 keys) V(16 keys x 64): bf16x3, 24 MMAs ----
            {
                const uint32_t vh = smb + SM_VHI +
                    (uint32_t)((ch * 16 + vrow) * PITCH + vcol) * 2;
                const uint32_t vl = smb + SM_VLO +
                    (uint32_t)((ch * 16 + vrow) * PITCH + vcol) * 2;
#pragma unroll
                for (int dd = 0; dd < 4; dd++) {
                    uint32_t bh[4], bl[4];
                    ldsm_x4_t(bh, vh + dd * 32);
                    ldsm_x4_t(bl, vl + dd * 32);
                    mma16816(o[2 * dd],     phi, bh[0], bh[1]);
                    mma16816(o[2 * dd + 1], phi, bh[2], bh[3]);
                    mma16816(o[2 * dd],     phi, bl[0], bl[1]);
                    mma16816(o[2 * dd + 1], phi, bl[2], bl[3]);
                    mma16816(o[2 * dd],     plo, bh[0], bh[1]);
                    mma16816(o[2 * dd + 1], plo, bh[2], bh[3]);
                }
            }
        }
        __syncthreads();   // smem tiles reusable
    }

    // ---- epilogue: reduce l across the quad, normalize, store ----
    lsum0 += __shfl_xor_sync(0xffffffffu, lsum0, 1);
    lsum0 += __shfl_xor_sync(0xffffffffu, lsum0, 2);
    lsum1 += __shfl_xor_sync(0xffffffffu, lsum1, 1);
    lsum1 += __shfl_xor_sync(0xffffffffu, lsum1, 2);
    const float inv0 = 1.0f / lsum0;
    const float inv1 = 1.0f / lsum1;

    const size_t r0 = (size_t)b * T_ + q0 + m0 + lq;
    const size_t r1 = r0 + 8;
#pragma unroll
    for (int dd = 0; dd < 8; dd++) {
        float2 w0 = { o[dd][0] * inv0, o[dd][1] * inv0 };
        float2 w1 = { o[dd][2] * inv1, o[dd][3] * inv1 };
        *(float2*)&out[r0 * D_ + dd * 8 + lc2] = w0;
        *(float2*)&out[r1 * D_ + dd * 8 + lc2] = w1;
    }
}

// ============================================================================
extern "C" void kernel_launch(void* const* d_in, const int* in_sizes, int n_in,
                              void* d_out, int out_size) {
    const float* x  = (const float*)d_in[0];
    const float* Wk = (const float*)d_in[1];
    const float* Wq = (const float*)d_in[2];
    const float* Wv = (const float*)d_in[3];
    float* out = (float*)d_out;
    (void)in_sizes; (void)n_in; (void)out_size;

    cudaFuncSetAttribute(attn_mma,
                         cudaFuncAttributeMaxDynamicSharedMemorySize,
                         SM_ATTN);

    proj_kernel<<<dim3(BT_ / 64, 3), 256>>>(x, Wk, Wq, Wv);
    attn_mma<<<B_ * (T_ / TQ), 256, SM_ATTN>>>(out);
}